// round 1
// baseline (speedup 1.0000x reference)
#include <cuda_runtime.h>
#include <cstdint>

#define BATCH 8
#define NPTS 200000
#define CH 32
#define RES 128
#define NBINS (RES * RES)
#define EPSF 1e-5f

// Scratch: accumulation in (b, plane, bin, channel) layout so that all 32
// channels of a bin form one contiguous 128B line -> red.global.add.v4.f32
// hits 16B-aligned segments.
__device__ float g_accum[(size_t)BATCH * 3 * NBINS * CH];   // ~50.3 MB
__device__ float g_cnt[(size_t)BATCH * 3 * NBINS];          // ~1.5 MB

__device__ __forceinline__ void red_add_v4(float* addr, float a, float b, float c, float d) {
    asm volatile("red.global.add.v4.f32 [%0], {%1, %2, %3, %4};"
                 :: "l"(addr), "f"(a), "f"(b), "f"(c), "f"(d)
                 : "memory");
}

__device__ __forceinline__ void red_add_f32(float* addr, float v) {
    asm volatile("red.global.add.f32 [%0], %1;"
                 :: "l"(addr), "f"(v)
                 : "memory");
}

__global__ void zero_scratch_kernel() {
    const size_t n4a = (size_t)BATCH * 3 * NBINS * CH / 4;
    const size_t n4c = (size_t)BATCH * 3 * NBINS / 4;
    float4 z = make_float4(0.f, 0.f, 0.f, 0.f);
    float4* a = reinterpret_cast<float4*>(g_accum);
    float4* c = reinterpret_cast<float4*>(g_cnt);
    size_t stride = (size_t)gridDim.x * blockDim.x;
    for (size_t i = (size_t)blockIdx.x * blockDim.x + threadIdx.x; i < n4a; i += stride)
        a[i] = z;
    for (size_t i = (size_t)blockIdx.x * blockDim.x + threadIdx.x; i < n4c; i += stride)
        c[i] = z;
}

__device__ __forceinline__ int to_bin(float v) {
    // Replicates reference float ops exactly:
    // t = (v - (-1))/2 - 0.5 ; t = t/(1+EPS) + 0.5 ; clamp [0, 1-EPS] ; floor(t*128)
    float t = (v + 1.0f) / 2.0f - 0.5f;
    t = t / (1.0f + EPSF) + 0.5f;
    t = fminf(fmaxf(t, 0.0f), 1.0f - EPSF);
    return (int)(t * 128.0f);
}

__global__ void scatter_kernel(const float* __restrict__ xyz,
                               const float* __restrict__ feat) {
    int idx = blockIdx.x * blockDim.x + threadIdx.x;
    if (idx >= BATCH * NPTS) return;
    int b = idx / NPTS;
    int n = idx - b * NPTS;

    const float* p = xyz + (size_t)idx * 3;
    float x = p[0], y = p[1], z = p[2];

    int ix = to_bin(x);
    int iy = to_bin(y);
    int iz = to_bin(z);

    // lin = idx0 + R*idx1 ; output pixel index == lin
    int bin_xy = ix + RES * iy;   // plane 0: dims (0,1)
    int bin_yz = iy + RES * iz;   // plane 1: dims (1,2)
    int bin_xz = ix + RES * iz;   // plane 2: dims (0,2)

    size_t base_b = (size_t)b * 3 * NBINS;
    red_add_f32(&g_cnt[base_b + 0 * NBINS + bin_xy], 1.0f);
    red_add_f32(&g_cnt[base_b + 1 * NBINS + bin_yz], 1.0f);
    red_add_f32(&g_cnt[base_b + 2 * NBINS + bin_xz], 1.0f);

    // Load all 32 channel values (coalesced: consecutive n across the warp).
    float f[CH];
    const float* fb = feat + (size_t)b * CH * NPTS + n;
#pragma unroll
    for (int c = 0; c < CH; c++)
        f[c] = __ldg(fb + (size_t)c * NPTS);

    float* a0 = g_accum + (base_b + (size_t)0 * NBINS + bin_xy) * CH;
    float* a1 = g_accum + (base_b + (size_t)1 * NBINS + bin_yz) * CH;
    float* a2 = g_accum + (base_b + (size_t)2 * NBINS + bin_xz) * CH;

#pragma unroll
    for (int c = 0; c < CH; c += 4) {
        red_add_v4(a0 + c, f[c], f[c + 1], f[c + 2], f[c + 3]);
        red_add_v4(a1 + c, f[c], f[c + 1], f[c + 2], f[c + 3]);
        red_add_v4(a2 + c, f[c], f[c + 1], f[c + 2], f[c + 3]);
    }
}

// Transpose (bin, channel) -> (channel, bin) while dividing by count.
// Block = 32x32, grid = (NBINS/32, 3, B).
__global__ void finalize_kernel(float* __restrict__ out) {
    __shared__ float tile[32][33];
    __shared__ float cnts[32];

    int pix0 = blockIdx.x * 32;
    int pl = blockIdx.y;
    int b = blockIdx.z;
    int tx = threadIdx.x;   // load phase: channel ; store phase: pixel offset
    int ty = threadIdx.y;   // load phase: pixel offset ; store phase: channel

    size_t base = ((size_t)b * 3 + pl) * NBINS;

    // coalesced load: 32 channels contiguous per bin row
    tile[ty][tx] = g_accum[(base + pix0 + ty) * CH + tx];
    if (ty == 0) cnts[tx] = g_cnt[base + pix0 + tx];
    __syncthreads();

    float cnt = fmaxf(cnts[tx], 1.0f);
    // coalesced store: consecutive pixels per warp
    out[(((size_t)b * 3 + pl) * CH + ty) * NBINS + pix0 + tx] = tile[tx][ty] / cnt;
}

extern "C" void kernel_launch(void* const* d_in, const int* in_sizes, int n_in,
                              void* d_out, int out_size) {
    const float* xyz = (const float*)d_in[0];    // (B, N, 3)
    const float* feat = (const float*)d_in[1];   // (B, C, N)
    float* out = (float*)d_out;                  // (B, 3, C, R, R)

    zero_scratch_kernel<<<2048, 256>>>();

    int total = BATCH * NPTS;
    scatter_kernel<<<(total + 255) / 256, 256>>>(xyz, feat);

    dim3 fgrid(NBINS / 32, 3, BATCH);
    dim3 fblk(32, 32);
    finalize_kernel<<<fgrid, fblk>>>(out);
}